// round 17
// baseline (speedup 1.0000x reference)
#include <cuda_runtime.h>

// LSTM: B=4096, T=256, F=18, H=64 (4H=256 gates i,f,g,o), classifier O=15.
// R17 = R16 with q-split across half-warps to kill duplicated weight reads:
//   warp (gsel, wrow): gsel = k-half (A: k0..31+f0..8, B: k32..63+f9..17),
//                      wrow = rows 8*wrow .. 8*wrow+7.
//   lane (qh, tg): qh = half-warp -> gate quads q in {2qh, 2qh+1};
//                  tg = cell group (cells tg+16c).
// Weight fetch: 2 LDS.128/k, halves read DIFFERENT quads (no duplication).
// Acts: 8 broadcast LDS.128 per 2k (one per row). acc = 8 rows x 2q x 2p.
// 4-way combine (grp = 2*gsel+qh): thread finalizes rows 8*wrow+2*grp+{0,1},
// cells tg+16c, all 4 gates. Full unroll; tanh.approx epilogue.

#define T_LEN 256
#define F_IN  18
#define H_DIM 64
#define G_DIM 256
#define O_DIM 15
#define ROWS  32
#define NTHR  256
#define NCTA  128
#define GK    32      // h-k steps per k-half
#define GF    9       // x-f steps per k-half

typedef unsigned long long u64;

#define HSTRIDE 66    // u64 per h row (64 data + 2 pad)

// ---- shared memory layout (bytes) ----
#define SM_WT    0                           // u64x2 wtq[82][64]        = 83968
#define SM_H     83968                       // u64 h[32][66]            = 16896
#define SM_X     (SM_H + 16896)              // u64 x[2][32][18]         = 9216
#define SM_RED   (SM_X + 9216)               // u64x2 red[4][4][4][64]   = 65536
#define SM_BS    (SM_RED + 65536)            // float bs[256]            = 1024
#define SM_WCLS  (SM_BS + 1024)              // float wcls[15*64]        = 3840
#define SM_BCLS  (SM_WCLS + 3840)            // float bcls[16]           = 64
#define SM_TOTAL (SM_BCLS + 64)              // 180544 (~176.3 KB)

__device__ __forceinline__ u64 pack2(float x, float y) {
    u64 r; asm("mov.b64 %0, {%1, %2};" : "=l"(r) : "f"(x), "f"(y)); return r;
}
__device__ __forceinline__ void unpack2(u64 v, float& x, float& y) {
    asm("mov.b64 {%0, %1}, %2;" : "=f"(x), "=f"(y) : "l"(v));
}
__device__ __forceinline__ void fma2(u64& d, u64 a, u64 b) {
    asm("fma.rn.f32x2 %0, %1, %2, %3;" : "=l"(d) : "l"(a), "l"(b), "l"(d));
}
__device__ __forceinline__ u64 add2v(u64 a, u64 b) {
    u64 d; asm("add.rn.f32x2 %0, %1, %2;" : "=l"(d) : "l"(a), "l"(b)); return d;
}
__device__ __forceinline__ ulonglong2 lds_v2(const void* p) {
    return *(const ulonglong2*)p;    // LDS.128 (16B-aligned by construction)
}

// hardware tanh (MUFU.TANH): 1 MUFU op, ~5e-4 max abs err
__device__ __forceinline__ float tanh_(float x) {
    float r; asm("tanh.approx.f32 %0, %1;" : "=f"(r) : "f"(x)); return r;
}
// sigmoid via tanh: sig(x) = 0.5*tanh(x/2) + 0.5
__device__ __forceinline__ float sig_(float x) {
    return fmaf(0.5f, tanh_(0.5f * x), 0.5f);
}

__global__ void __launch_bounds__(NTHR, 1) lstm_kernel(
    const float* __restrict__ X,      // [B,T,F]
    const float* __restrict__ W_ih,   // [4H,F]
    const float* __restrict__ W_hh,   // [4H,H]
    const float* __restrict__ b_ih,   // [4H]
    const float* __restrict__ b_hh,   // [4H]
    const float* __restrict__ W_cls,  // [O,H]
    const float* __restrict__ b_cls,  // [O]
    float* __restrict__ out)          // [B,O]
{
    extern __shared__ char sm[];
    ulonglong2* wtq  = (ulonglong2*)(sm + SM_WT);   // wtq[k*64 + q*16 + tg]
    u64*        hbuf = (u64*)       (sm + SM_H);
    ulonglong2* red2 = (ulonglong2*)(sm + SM_RED);  // red[src][dst][slot][64]
    float*      bs   = (float*)     (sm + SM_BS);
    float*      wcls = (float*)     (sm + SM_WCLS);
    float*      bcl  = (float*)     (sm + SM_BCLS);

    const int tid  = threadIdx.x;
    const int wid  = tid >> 5;
    const int gsel = wid >> 2;          // k-half
    const int wrow = wid & 3;           // rows 8*wrow .. 8*wrow+7
    const int lane = tid & 31;
    const int qh   = lane >> 4;         // gate quads q in {2qh, 2qh+1}
    const int tg   = lane & 15;         // cells tg + 16c
    const int grp  = 2 * gsel + qh;     // combine group 0..3
    const int lgrp = wrow * 16 + tg;    // 0..63: lane slot within a grp
    const int row0 = blockIdx.x * ROWS;
    const int wofs0 = 32 * qh + tg;     // ulonglong2 col of quad q=2qh
    const int wofs1 = wofs0 + 16;       // quad q=2qh+1

    // red[src][dst][slot(rl*2+qq)] (x64 lanes)
#define RED(s, d, slot) ((((s) * 16) + ((d) * 4) + (slot)) * 64 + lgrp)

    // ---- one-time setup: quad-pack weights ----
    // wtq[k*64 + q*16 + tgx] = { {W[g0],W[g0+16]}, {W[g0+32],W[g0+48]} }, g0 = 64q+tgx
    for (int i = tid; i < (H_DIM + F_IN) * 64; i += NTHR) {
        int k = i >> 6, col = i & 63;
        int q = col >> 4, tgx = col & 15;
        int g0 = 64 * q + tgx;
        float a, b, c, d;
        if (k < H_DIM) {
            a = W_hh[g0 * H_DIM + k];
            b = W_hh[(g0 + 16) * H_DIM + k];
            c = W_hh[(g0 + 32) * H_DIM + k];
            d = W_hh[(g0 + 48) * H_DIM + k];
        } else {
            int f = k - H_DIM;
            a = W_ih[g0 * F_IN + f];
            b = W_ih[(g0 + 16) * F_IN + f];
            c = W_ih[(g0 + 32) * F_IN + f];
            d = W_ih[(g0 + 48) * F_IN + f];
        }
        ulonglong2 v; v.x = pack2(a, b); v.y = pack2(c, d);
        wtq[i] = v;
    }
    for (int g = tid; g < G_DIM; g += NTHR) bs[g] = b_ih[g] + b_hh[g];
    for (int i = tid; i < O_DIM * H_DIM; i += NTHR) wcls[i] = W_cls[i];
    if (tid < O_DIM) bcl[tid] = b_cls[tid];
    for (int i = tid; i < ROWS * HSTRIDE; i += NTHR) hbuf[i] = 0ull;  // h(-1)=0

    // X prefetch mapping over all 256 threads: 3 slots cover 32x18 = 576
    int pb[3], pf[3]; bool pv[3];
#pragma unroll
    for (int m = 0; m < 3; m++) {
        int e = tid + NTHR * m;
        pv[m] = (e < ROWS * F_IN);
        int b = e / F_IN;
        pb[m] = b;
        pf[m] = e - b * F_IN;
    }
    const float* Xbase = X + (long long)row0 * T_LEN * F_IN;

    // stage x(0) into xbuf[0]
    {
        u64* x0 = (u64*)(sm + SM_X);
#pragma unroll
        for (int m = 0; m < 3; m++)
            if (pv[m]) {
                float v = Xbase[(long long)pb[m] * (T_LEN * F_IN) + pf[m]];
                x0[pb[m] * F_IN + pf[m]] = pack2(v, v);
            }
    }
    __syncthreads();   // bs visible for biasv packing

    // biases for MY 2 q's: biasv[qq][p], q = 2qh+qq
    u64 biasv[2][2];
#pragma unroll
    for (int qq = 0; qq < 2; qq++) {
        int g0 = 64 * (2 * qh + qq) + tg;
        biasv[qq][0] = pack2(bs[g0],      bs[g0 + 16]);
        biasv[qq][1] = pack2(bs[g0 + 32], bs[g0 + 48]);
    }

    // cell state: rows 8*wrow + 2*grp + {0,1}, cells tg + 16c
    float creg[2][4];
#pragma unroll
    for (int r = 0; r < 2; r++)
#pragma unroll
        for (int c = 0; c < 4; c++) creg[r][c] = 0.0f;

    const int hab = 8 * wrow * HSTRIDE;
    const int xab = 8 * wrow * F_IN;
    const int kh0 = gsel * GK;          // h-k start for this k-half
    const int xf0 = gsel * GF;          // x-f start for this k-half
    int buf = 0;

    __syncthreads();   // setup + x(0) + h(-1) visible

    // ================= time loop =================
    for (int t = 0; t < T_LEN; ++t) {
        const u64* xb  = (const u64*)(sm + SM_X) + buf * (ROWS * F_IN);
        u64*       xb2 = (u64*)(sm + SM_X) + (buf ^ 1) * (ROWS * F_IN);

        // issue x(t+1) global loads first (latency hidden under x+h parts)
        float xp[3];
        if (t + 1 < T_LEN) {
#pragma unroll
            for (int m = 0; m < 3; m++)
                xp[m] = pv[m]
                    ? Xbase[(long long)pb[m] * (T_LEN * F_IN) + (t + 1) * F_IN + pf[m]]
                    : 0.0f;
        }

        // bias contributed once (gsel==0 side), all 8 rows
        u64 acc[8][2][2];
#pragma unroll
        for (int r = 0; r < 8; r++)
#pragma unroll
            for (int qq = 0; qq < 2; qq++)
#pragma unroll
                for (int p = 0; p < 2; p++)
                    acc[r][qq][p] = (gsel == 0) ? biasv[qq][p] : 0ull;

        // ---- x-part: this k-half's 9 f's (FULL unroll) ----
#pragma unroll
        for (int ff = 0; ff < GF; ff++) {
            int f = xf0 + ff;
            u64 a[8];
#pragma unroll
            for (int r = 0; r < 8; r++) a[r] = xb[xab + r * F_IN + f];
            const ulonglong2* wrp = wtq + (H_DIM + f) * 64;
            ulonglong2 w0 = lds_v2(wrp + wofs0);   // quad q=2qh
            ulonglong2 w1 = lds_v2(wrp + wofs1);   // quad q=2qh+1
#pragma unroll
            for (int r = 0; r < 8; r++) {
                fma2(acc[r][0][0], a[r], w0.x); fma2(acc[r][0][1], a[r], w0.y);
                fma2(acc[r][1][0], a[r], w1.x); fma2(acc[r][1][1], a[r], w1.y);
            }
        }

        __syncthreads();   // bar1: h(t-1) stores visible; red(t-1) readers done

        // ---- h-part: this k-half's 32 k's, FULL unroll (16 k-pair bodies) ----
#pragma unroll
        for (int kk = 0; kk < GK; kk += 2) {
            int k = kh0 + kk;
            ulonglong2 A[8];
#pragma unroll
            for (int r = 0; r < 8; r++)
                A[r] = lds_v2(&hbuf[hab + r * HSTRIDE + k]);   // {h_k, h_k+1}
            const ulonglong2* wk0 = wtq + k * 64;
            const ulonglong2* wk1 = wk0 + 64;
            ulonglong2 w00 = lds_v2(wk0 + wofs0);
            ulonglong2 w01 = lds_v2(wk0 + wofs1);
            ulonglong2 w10 = lds_v2(wk1 + wofs0);
            ulonglong2 w11 = lds_v2(wk1 + wofs1);
#pragma unroll
            for (int r = 0; r < 8; r++) {
                fma2(acc[r][0][0], A[r].x, w00.x); fma2(acc[r][0][1], A[r].x, w00.y);
                fma2(acc[r][1][0], A[r].x, w01.x); fma2(acc[r][1][1], A[r].x, w01.y);
                fma2(acc[r][0][0], A[r].y, w10.x); fma2(acc[r][0][1], A[r].y, w10.y);
                fma2(acc[r][1][0], A[r].y, w11.x); fma2(acc[r][1][1], A[r].y, w11.y);
            }
        }

        // ---- keep my 2 rows; send the other 6 rows' partials ----
        u64 own[2][2][2];   // [rl][qq][p]
#pragma unroll
        for (int d = 0; d < 4; d++) {
            if (d == grp) {
#pragma unroll
                for (int rl = 0; rl < 2; rl++)
#pragma unroll
                    for (int qq = 0; qq < 2; qq++)
#pragma unroll
                        for (int p = 0; p < 2; p++)
                            own[rl][qq][p] = acc[2 * d + rl][qq][p];
            } else {
#pragma unroll
                for (int rl = 0; rl < 2; rl++)
#pragma unroll
                    for (int qq = 0; qq < 2; qq++) {
                        ulonglong2 v;
                        v.x = acc[2 * d + rl][qq][0];
                        v.y = acc[2 * d + rl][qq][1];
                        red2[RED(grp, d, rl * 2 + qq)] = v;   // STS.128
                    }
            }
        }

        // publish x(t+1) BEFORE bar2
        if (t + 1 < T_LEN) {
#pragma unroll
            for (int m = 0; m < 3; m++)
                if (pv[m]) xb2[pb[m] * F_IN + pf[m]] = pack2(xp[m], xp[m]);
        }

        __syncthreads();   // bar2: partials + x(t+1) visible; h readers done

        // ---- combine + cell update per finalized row ----
#pragma unroll
        for (int rl = 0; rl < 2; rl++) {
            // same-q, other k-half:
            ulonglong2 m0 = red2[RED(grp ^ 2, grp, rl * 2 + 0)];
            ulonglong2 m1 = red2[RED(grp ^ 2, grp, rl * 2 + 1)];
            // other-q pair, both k-halves:
            ulonglong2 oa0 = red2[RED(grp ^ 1, grp, rl * 2 + 0)];
            ulonglong2 oa1 = red2[RED(grp ^ 1, grp, rl * 2 + 1)];
            ulonglong2 ob0 = red2[RED(grp ^ 3, grp, rl * 2 + 0)];
            ulonglong2 ob1 = red2[RED(grp ^ 3, grp, rl * 2 + 1)];

            u64 fmine[2][2], foth[2][2];
            fmine[0][0] = add2v(own[rl][0][0], m0.x);
            fmine[0][1] = add2v(own[rl][0][1], m0.y);
            fmine[1][0] = add2v(own[rl][1][0], m1.x);
            fmine[1][1] = add2v(own[rl][1][1], m1.y);
            foth[0][0]  = add2v(oa0.x, ob0.x);
            foth[0][1]  = add2v(oa0.y, ob0.y);
            foth[1][0]  = add2v(oa1.x, ob1.x);
            foth[1][1]  = add2v(oa1.y, ob1.y);

            // gv[q][c]: q 0..3 = i,f,g,o ; c: 0->tg,1->tg+16,2->tg+32,3->tg+48
            float gv[4][4];
            if (qh == 0) {   // mine = q0,q1 ; other = q2,q3
#pragma unroll
                for (int qq = 0; qq < 2; qq++) {
                    unpack2(fmine[qq][0], gv[qq][0], gv[qq][1]);
                    unpack2(fmine[qq][1], gv[qq][2], gv[qq][3]);
                    unpack2(foth[qq][0],  gv[2 + qq][0], gv[2 + qq][1]);
                    unpack2(foth[qq][1],  gv[2 + qq][2], gv[2 + qq][3]);
                }
            } else {         // mine = q2,q3 ; other = q0,q1
#pragma unroll
                for (int qq = 0; qq < 2; qq++) {
                    unpack2(foth[qq][0],  gv[qq][0], gv[qq][1]);
                    unpack2(foth[qq][1],  gv[qq][2], gv[qq][3]);
                    unpack2(fmine[qq][0], gv[2 + qq][0], gv[2 + qq][1]);
                    unpack2(fmine[qq][1], gv[2 + qq][2], gv[2 + qq][3]);
                }
            }

            int base = (8 * wrow + 2 * grp + rl) * HSTRIDE + tg;
#pragma unroll
            for (int c = 0; c < 4; c++) {
                float iv = sig_(gv[0][c]);
                float fv = sig_(gv[1][c]);
                float gg = tanh_(gv[2][c]);
                float ov = sig_(gv[3][c]);
                float cc = fv * creg[rl][c] + iv * gg;
                creg[rl][c] = cc;
                float hv = ov * tanh_(cc);
                hbuf[base + 16 * c] = pack2(hv, hv);
            }
        }

        buf ^= 1;
    }

    // ---- classifier head on final h ----
    __syncthreads();
    const float* hf = (const float*)hbuf;

    for (int e = tid; e < ROWS * O_DIM; e += NTHR) {
        int b = e / O_DIM, o = e - b * O_DIM;
        float s = bcl[o];
#pragma unroll
        for (int j = 0; j < H_DIM; j++)
            s += hf[(b * HSTRIDE + j) * 2] * wcls[o * H_DIM + j];
        out[(long long)(row0 + b) * O_DIM + o] = s;
    }
#undef RED
}

extern "C" void kernel_launch(void* const* d_in, const int* in_sizes, int n_in,
                              void* d_out, int out_size)
{
    const float* X     = (const float*)d_in[0];
    const float* W_ih  = (const float*)d_in[1];
    const float* W_hh  = (const float*)d_in[2];
    const float* b_ih  = (const float*)d_in[3];
    const float* b_hh  = (const float*)d_in[4];
    const float* W_cls = (const float*)d_in[5];
    const float* b_cls = (const float*)d_in[6];

    cudaFuncSetAttribute(lstm_kernel,
                         cudaFuncAttributeMaxDynamicSharedMemorySize, SM_TOTAL);
    lstm_kernel<<<NCTA, NTHR, SM_TOTAL>>>(X, W_ih, W_hh, b_ih, b_hh,
                                          W_cls, b_cls, (float*)d_out);
}